// round 3
// baseline (speedup 1.0000x reference)
#include <cuda_runtime.h>
#include <cstdint>

#define NMAX 250000
#define EMAX 4000000
#define HID  16

// ---- scratch (static __device__ globals; no allocation allowed) ----
__device__ float  d_deg[NMAX];
__device__ float  d_dinv[NMAX];
__device__ float  d_q[NMAX];       // dinv[i]*x[i]
__device__ float  d_s1raw[NMAX];   // sum over edges of q[row]
__device__ __align__(16) float2 d_g[NMAX];    // {dinv[i], s1[i]}
__device__ __align__(16) float  d_agg2[NMAX * HID];

// ---------------- kernels ----------------

// zero agg2 + s1raw, deg=1 (self-loop)
__global__ void k_init(int n) {
    int i = blockIdx.x * blockDim.x + threadIdx.x;
    int total = n * HID;
    for (; i < total; i += gridDim.x * blockDim.x) {
        d_agg2[i] = 0.0f;
        if (i < n) { d_s1raw[i] = 0.0f; d_deg[i] = 1.0f; }
    }
}

// degree count over col (edge_index is int32: JAX x64 disabled)
__global__ void k_deg(const int* __restrict__ ei, int E, int n) {
    int e = blockIdx.x * blockDim.x + threadIdx.x;
    for (; e < E; e += gridDim.x * blockDim.x) {
        int c = ei[E + e];
        if ((unsigned)c < (unsigned)n)
            atomicAdd(d_deg + c, 1.0f);
    }
}

// dinv = rsqrt(deg); q = dinv*x
__global__ void k_node1(const float* __restrict__ x, int n) {
    int i = blockIdx.x * blockDim.x + threadIdx.x;
    if (i < n) {
        float di = rsqrtf(d_deg[i]);   // deg >= 1 always (self-loop)
        d_dinv[i] = di;
        d_q[i] = di * x[i];
    }
}

// layer-1 scalar aggregation: s1raw[col] += q[row]
__global__ void k_edge1(const int* __restrict__ ei, int E, int n) {
    int e = blockIdx.x * blockDim.x + threadIdx.x;
    for (; e < E; e += gridDim.x * blockDim.x) {
        int r = ei[e];
        int c = ei[E + e];
        if ((unsigned)r < (unsigned)n && (unsigned)c < (unsigned)n)
            atomicAdd(d_s1raw + c, __ldg(d_q + r));
    }
}

// s1[i] = dinv[i]*(s1raw[i] + q[i])  (q term = self-loop); pack g = {dinv, s1}
__global__ void k_node2(int n) {
    int i = blockIdx.x * blockDim.x + threadIdx.x;
    if (i < n) {
        float di = d_dinv[i];
        float s1 = di * (d_s1raw[i] + d_q[i]);
        d_g[i] = make_float2(di, s1);
    }
}

// layer-2 edge pass: agg2[col][:] += dinv[row] * relu(s1[row]*W1 + b1)
__global__ void k_edge2(const int* __restrict__ ei,
                        const float* __restrict__ W1, const float* __restrict__ b1,
                        int E, int n) {
    float w[HID], bb[HID];
#pragma unroll
    for (int k = 0; k < HID; k++) { w[k] = __ldg(W1 + k); bb[k] = __ldg(b1 + k); }
    int stride = gridDim.x * blockDim.x;
    for (int e = blockIdx.x * blockDim.x + threadIdx.x; e < E; e += stride) {
        int r = ei[e];
        int c = ei[E + e];
        if ((unsigned)r >= (unsigned)n || (unsigned)c >= (unsigned)n) continue;
        float2 gr = __ldg(d_g + r);
        float m[HID];
#pragma unroll
        for (int k = 0; k < HID; k++) {
            float h = fmaf(gr.y, w[k], bb[k]);
            h = fmaxf(h, 0.0f);
            m[k] = gr.x * h;
        }
        float* dst = d_agg2 + (size_t)c * HID;
#pragma unroll
        for (int k = 0; k < HID; k += 4) {
            asm volatile("red.global.add.v4.f32 [%0], {%1, %2, %3, %4};"
                         :: "l"(dst + k), "f"(m[k]), "f"(m[k + 1]), "f"(m[k + 2]), "f"(m[k + 3])
                         : "memory");
        }
    }
}

// node epilogue: add self-loop, apply dinv[col], W2+b2+relu, Wfc+bfc
__global__ void k_out(const float* __restrict__ W1, const float* __restrict__ b1,
                      const float* __restrict__ W2, const float* __restrict__ b2,
                      const float* __restrict__ Wfc, const float* __restrict__ bfc,
                      float* __restrict__ out, int n) {
    int i = blockIdx.x * blockDim.x + threadIdx.x;
    if (i >= n) return;
    float2 gi = d_g[i];
    float di = gi.x, s1 = gi.y;
    float afull[HID];
#pragma unroll
    for (int k = 0; k < HID; k++) {
        float h1 = fmaxf(fmaf(s1, __ldg(W1 + k), __ldg(b1 + k)), 0.0f);
        // agg2_full = dinv[i]*(agg2raw + dinv[i]*h1)   (self-loop folded in)
        afull[k] = di * (d_agg2[(size_t)i * HID + k] + di * h1);
    }
    float h2[HID];
#pragma unroll
    for (int j = 0; j < HID; j++) {
        float acc = __ldg(b2 + j);
#pragma unroll
        for (int k = 0; k < HID; k++) acc = fmaf(afull[k], __ldg(W2 + k * HID + j), acc);
        h2[j] = fmaxf(acc, 0.0f);
    }
#pragma unroll
    for (int j = 0; j < 4; j++) {
        float acc = __ldg(bfc + j);
#pragma unroll
        for (int k = 0; k < HID; k++) acc = fmaf(h2[k], __ldg(Wfc + k * 4 + j), acc);
        out[(size_t)i * 4 + j] = acc;
    }
}

// ---------------- launch ----------------

extern "C" void kernel_launch(void* const* d_in, const int* in_sizes, int n_in,
                              void* d_out, int out_size) {
    const float* x   = (const float*)d_in[0];
    const int*   ei  = (const int*)d_in[1];     // int32 (JAX x64 disabled)
    const float* W1  = (const float*)d_in[2];
    const float* b1  = (const float*)d_in[3];
    const float* W2  = (const float*)d_in[4];
    const float* b2  = (const float*)d_in[5];
    const float* Wfc = (const float*)d_in[6];
    const float* bfc = (const float*)d_in[7];
    float* out = (float*)d_out;

    int n = in_sizes[0];        // x is [N, 1]
    int E = in_sizes[1] / 2;    // edge_index is [2, E]

    const int T = 256;
    int nb_nodes = (n + T - 1) / T;
    int nb_init  = (n * HID + T - 1) / T;
    int nb_edges = (E + T - 1) / T;
    if (nb_edges > 16384) nb_edges = 16384;
    int nb_e2 = 148 * 16;  // grid-stride, amortize weight loads

    k_init <<<nb_init,  T>>>(n);
    k_deg  <<<nb_edges, T>>>(ei, E, n);
    k_node1<<<nb_nodes, T>>>(x, n);
    k_edge1<<<nb_edges, T>>>(ei, E, n);
    k_node2<<<nb_nodes, T>>>(n);
    k_edge2<<<nb_e2,    T>>>(ei, W1, b1, E, n);
    k_out  <<<nb_nodes, T>>>(W1, b1, W2, b2, Wfc, bfc, out, n);
}

// round 4
// speedup vs baseline: 1.5261x; 1.5261x over previous
#include <cuda_runtime.h>
#include <cstdint>
#include <cfloat>

#define NMAX 250000
#define EMAX 4000000
#define HID  16
#define NBIN 17   // 16 thresholds -> 17 intervals

// ---- scratch (static __device__ globals) ----
__device__ float  d_deg[NMAX];
__device__ float  d_q[NMAX];        // dinv*x
__device__ float  d_s1raw[NMAX];
__device__ __align__(16) float2 d_g[NMAX];    // {dinv, s1}
__device__ __align__(16) float4 d_nd[NMAX];   // {a=dinv*s1, d=dinv, j(bits), 0}
__device__ __align__(16) float2 d_bins[NBIN * NMAX];  // [j][node] -> {sumA, sumD}, 34MB
__device__ float  d_t[HID];         // thresholds
__device__ int    d_r[HID];         // rank_k = #{k': t_k' < t_k}

// ---------------- kernels ----------------

// zero bins (as float4), s1raw=0, deg=1; block0/thread0 computes thresholds+ranks
__global__ void k_init(const float* __restrict__ W1, const float* __restrict__ b1, int n) {
    int i = blockIdx.x * blockDim.x + threadIdx.x;
    const int nb4 = NBIN * NMAX / 2;            // float4 count of d_bins
    float4* bins4 = reinterpret_cast<float4*>(d_bins);
    for (int t = i; t < nb4; t += gridDim.x * blockDim.x)
        bins4[t] = make_float4(0.f, 0.f, 0.f, 0.f);
    if (i < n) { d_s1raw[i] = 0.0f; d_deg[i] = 1.0f; }
    if (blockIdx.x == 0 && threadIdx.x == 0) {
        float t[HID];
        for (int k = 0; k < HID; k++) {
            float w = W1[k], b = b1[k];
            t[k] = (w != 0.0f) ? (-b / w) : -FLT_MAX;
            d_t[k] = t[k];
        }
        for (int k = 0; k < HID; k++) {
            int r = 0;
            for (int k2 = 0; k2 < HID; k2++) r += (t[k2] < t[k]);
            d_r[k] = r;
        }
    }
}

// degree over targets
__global__ void k_deg(const int* __restrict__ ei, int E, int n) {
    int e = blockIdx.x * blockDim.x + threadIdx.x;
    if (e < E) {
        int c = ei[E + e];
        if ((unsigned)c < (unsigned)n) atomicAdd(d_deg + c, 1.0f);
    }
}

// q = rsqrt(deg)*x
__global__ void k_node1(const float* __restrict__ x, int n) {
    int i = blockIdx.x * blockDim.x + threadIdx.x;
    if (i < n) {
        float di = rsqrtf(d_deg[i]);
        d_q[i] = di * x[i];
        d_g[i].x = di;              // stash dinv
    }
}

// s1raw[col] += q[row]
__global__ void k_edge1(const int* __restrict__ ei, int E, int n) {
    int e = blockIdx.x * blockDim.x + threadIdx.x;
    if (e < E) {
        int r = ei[e];
        int c = ei[E + e];
        if ((unsigned)r < (unsigned)n && (unsigned)c < (unsigned)n)
            atomicAdd(d_s1raw + c, __ldg(d_q + r));
    }
}

// s1 = dinv*(s1raw + q)  [q term = self-loop]; pack nd = {dinv*s1, dinv, j}
__global__ void k_node2(int n) {
    __shared__ float st[HID];
    if (threadIdx.x < HID) st[threadIdx.x] = d_t[threadIdx.x];
    __syncthreads();
    int i = blockIdx.x * blockDim.x + threadIdx.x;
    if (i < n) {
        float di = d_g[i].x;
        float s1 = di * (d_s1raw[i] + d_q[i]);
        d_g[i] = make_float2(di, s1);
        int j = 0;
#pragma unroll
        for (int k = 0; k < HID; k++) j += (st[k] < s1);
        d_nd[i] = make_float4(di * s1, di, __int_as_float(j), 0.0f);
    }
}

// layer-2 binned scatter: bins[j(row)][col] += {a_row, d_row}
__global__ void k_edge2(const int* __restrict__ ei, int E, int n) {
    int e = blockIdx.x * blockDim.x + threadIdx.x;
    if (e < E) {
        int r = ei[e];
        int c = ei[E + e];
        if ((unsigned)r < (unsigned)n && (unsigned)c < (unsigned)n) {
            float4 nd = __ldg(d_nd + r);
            int j = __float_as_int(nd.z);
            float2* dst = d_bins + (size_t)j * NMAX + c;
            asm volatile("red.global.add.v2.f32 [%0], {%1, %2};"
                         :: "l"(dst), "f"(nd.x), "f"(nd.y) : "memory");
        }
    }
}

// fused epilogue: reconstruct agg2 from bins, self-loop, dinv, W2+relu, Wfc -> out
__global__ void k_out(const float* __restrict__ W1, const float* __restrict__ b1,
                      const float* __restrict__ W2, const float* __restrict__ b2,
                      const float* __restrict__ Wfc, const float* __restrict__ bfc,
                      float* __restrict__ out, int n) {
    __shared__ float sW2[HID * HID], sWfc[HID * 4];
    __shared__ float sw1[HID], sb1[HID], sb2[HID], sbfc[4];
    __shared__ int   sr[HID];
    int t = threadIdx.x;
    if (t < HID * HID) sW2[t] = W2[t];
    if (t < HID * 4)   sWfc[t] = Wfc[t];
    if (t < HID) { sw1[t] = W1[t]; sb1[t] = b1[t]; sb2[t] = b2[t]; sr[t] = d_r[t]; }
    if (t < 4)   sbfc[t] = bfc[t];
    __syncthreads();

    int i = blockIdx.x * blockDim.x + t;
    if (i >= n) return;

    float aa[NBIN], dd[NBIN];
    float TA = 0.f, TD = 0.f;
#pragma unroll
    for (int j = 0; j < NBIN; j++) {
        float2 b = __ldg(d_bins + (size_t)j * NMAX + i);
        aa[j] = b.x; dd[j] = b.y;
        TA += b.x; TD += b.y;
    }
    float2 gi = d_g[i];
    float di = gi.x, s1 = gi.y;

    float afull[HID];
#pragma unroll
    for (int k = 0; k < HID; k++) {
        float wk = sw1[k], bk = sb1[k];
        int   rk = sr[k];
        float A = 0.f, D = 0.f;
        if (wk > 0.f) {
#pragma unroll
            for (int j = 0; j < NBIN; j++) if (j > rk) { A += aa[j]; D += dd[j]; }
        } else if (wk < 0.f) {
#pragma unroll
            for (int j = 0; j < NBIN; j++) if (j <= rk) { A += aa[j]; D += dd[j]; }
        } else {
            A = 0.f; D = (bk > 0.f) ? TD : 0.f;
        }
        float agg = fmaf(wk, A, bk * D);                 // sum over real edges
        float h1c = fmaxf(fmaf(s1, wk, bk), 0.f);        // self-loop message
        afull[k] = di * fmaf(di, h1c, agg);
    }
    float h2[HID];
#pragma unroll
    for (int j = 0; j < HID; j++) {
        float acc = sb2[j];
#pragma unroll
        for (int k = 0; k < HID; k++) acc = fmaf(afull[k], sW2[k * HID + j], acc);
        h2[j] = fmaxf(acc, 0.f);
    }
#pragma unroll
    for (int j = 0; j < 4; j++) {
        float acc = sbfc[j];
#pragma unroll
        for (int k = 0; k < HID; k++) acc = fmaf(h2[k], sWfc[k * 4 + j], acc);
        out[(size_t)i * 4 + j] = acc;
    }
}

// ---------------- launch ----------------

extern "C" void kernel_launch(void* const* d_in, const int* in_sizes, int n_in,
                              void* d_out, int out_size) {
    const float* x   = (const float*)d_in[0];
    const int*   ei  = (const int*)d_in[1];     // int32 (JAX x64 disabled)
    const float* W1  = (const float*)d_in[2];
    const float* b1  = (const float*)d_in[3];
    const float* W2  = (const float*)d_in[4];
    const float* b2  = (const float*)d_in[5];
    const float* Wfc = (const float*)d_in[6];
    const float* bfc = (const float*)d_in[7];
    float* out = (float*)d_out;

    int n = in_sizes[0];
    int E = in_sizes[1] / 2;

    const int T = 256;
    int nb_nodes = (n + T - 1) / T;
    int nb_edges = (E + T - 1) / T;
    int nb_init  = (NBIN * NMAX / 2 + T - 1) / T;   // float4 elements of bins

    k_init <<<nb_init,  T>>>(W1, b1, n);
    k_deg  <<<nb_edges, T>>>(ei, E, n);
    k_node1<<<nb_nodes, T>>>(x, n);
    k_edge1<<<nb_edges, T>>>(ei, E, n);
    k_node2<<<nb_nodes, T>>>(n);
    k_edge2<<<nb_edges, T>>>(ei, E, n);
    k_out  <<<nb_nodes, T>>>(W1, b1, W2, b2, Wfc, bfc, out, n);
}